// round 15
// baseline (speedup 1.0000x reference)
#include <cuda_runtime.h>
#include <cuda_fp16.h>
#include <math.h>
#include <stdint.h>

#define BB 4
#define SS 2048
#define DD 1024
#define FF 4096
#define HH 16
#define QKVD (3*DD)
#define NEGBIG -1e30f
#define MROWS (BB*SS)
#define M1 (DD*DD)
// 0.125 * log2(e) folded into Q
#define QSCALE 0.1803368801111204f

// ---------------- scratch ------------------------------------------------------
__device__ __half g_x16 [MROWS*DD];
__device__ __half g_qkv16[(size_t)MROWS*QKVD];
__device__ __half g_ctx16[MROWS*DD];
__device__ float  g_x2  [MROWS*DD];
__device__ __half g_y16 [MROWS*DD];
__device__ __half g_h16 [(size_t)MROWS*FF];
__device__ __half g_w16[(size_t)12*M1];

// ---------------- helpers ------------------------------------------------------
__device__ __forceinline__ uint32_t pk16(float a, float b) {
    __half2 h = __floats2half2_rn(a, b);
    return *reinterpret_cast<uint32_t*>(&h);
}
__device__ __forceinline__ float ex2f(float x) {
    float r;
    asm("ex2.approx.f32 %0, %1;" : "=f"(r) : "f"(x));
    return r;
}
__device__ __forceinline__ void hmma16(float* d, uint32_t a0, uint32_t a1,
                                       uint32_t a2, uint32_t a3,
                                       uint32_t b0, uint32_t b1) {
    asm volatile("mma.sync.aligned.m16n8k16.row.col.f32.f16.f16.f32 "
                 "{%0,%1,%2,%3}, {%4,%5,%6,%7}, {%8,%9}, {%0,%1,%2,%3};"
                 : "+f"(d[0]), "+f"(d[1]), "+f"(d[2]), "+f"(d[3])
                 : "r"(a0), "r"(a1), "r"(a2), "r"(a3), "r"(b0), "r"(b1));
}
__device__ __forceinline__ uint32_t s2u(const void* p) {
    return (uint32_t)__cvta_generic_to_shared(p);
}
__device__ __forceinline__ void cp16(uint32_t dst, const void* src) {
    asm volatile("cp.async.ca.shared.global [%0], [%1], 16;" :: "r"(dst), "l"(src));
}
__device__ __forceinline__ void cp_commit() { asm volatile("cp.async.commit_group;"); }
__device__ __forceinline__ void cp_wait0()  { asm volatile("cp.async.wait_group 0;"); }
__device__ __forceinline__ void cp_wait1()  { asm volatile("cp.async.wait_group 1;"); }
__device__ __forceinline__ void ldm4(uint32_t addr, uint32_t& r0, uint32_t& r1,
                                     uint32_t& r2, uint32_t& r3) {
    asm volatile("ldmatrix.sync.aligned.m8n8.x4.shared.b16 {%0,%1,%2,%3}, [%4];"
                 : "=r"(r0), "=r"(r1), "=r"(r2), "=r"(r3) : "r"(addr));
}
__device__ __forceinline__ void ldm4t(uint32_t addr, uint32_t& r0, uint32_t& r1,
                                      uint32_t& r2, uint32_t& r3) {
    asm volatile("ldmatrix.sync.aligned.m8n8.x4.trans.shared.b16 {%0,%1,%2,%3}, [%4];"
                 : "=r"(r0), "=r"(r1), "=r"(r2), "=r"(r3) : "r"(addr));
}

// ---------------- LayerNorm -> single fp16 -------------------------------------
__global__ __launch_bounds__(256)
void ln_f16(const float* __restrict__ x, const float* __restrict__ g,
            const float* __restrict__ b, __half* __restrict__ out16)
{
    int row = blockIdx.x;
    int tid = threadIdx.x;
    const float* xr = x + (size_t)row * DD;
    float4 v = *reinterpret_cast<const float4*>(xr + tid * 4);
    float s  = v.x + v.y + v.z + v.w;
    float sq = v.x*v.x + v.y*v.y + v.z*v.z + v.w*v.w;
    #pragma unroll
    for (int o = 16; o > 0; o >>= 1) {
        s  += __shfl_xor_sync(0xffffffffu, s,  o);
        sq += __shfl_xor_sync(0xffffffffu, sq, o);
    }
    __shared__ float ws[8], wq[8];
    __shared__ float smean, srstd;
    int wid = tid >> 5, lane = tid & 31;
    if (lane == 0) { ws[wid] = s; wq[wid] = sq; }
    __syncthreads();
    if (tid == 0) {
        float S = 0.f, Q = 0.f;
        #pragma unroll
        for (int i = 0; i < 8; i++) { S += ws[i]; Q += wq[i]; }
        float mean = S * (1.f / DD);
        float var  = fmaxf(Q * (1.f / DD) - mean * mean, 0.f);
        smean = mean;
        srstd = rsqrtf(var + 1e-12f);
    }
    __syncthreads();
    float mean = smean, rstd = srstd;
    float4 gv = *reinterpret_cast<const float4*>(g + tid * 4);
    float4 bv = *reinterpret_cast<const float4*>(b + tid * 4);
    uint2 pk = make_uint2(
        pk16((v.x - mean) * rstd * gv.x + bv.x, (v.y - mean) * rstd * gv.y + bv.y),
        pk16((v.z - mean) * rstd * gv.z + bv.z, (v.w - mean) * rstd * gv.w + bv.w));
    *reinterpret_cast<uint2*>(out16 + (size_t)row * DD + tid * 4) = pk;
}

// ---------------- batched weight transpose -> fp16 ------------------------------
// z<4: DxD weights (Wq,Wk,Wv,Wo). z==4: W1 [DD,FF]. z==5: W2 [FF,DD].
__global__ __launch_bounds__(256)
void trans16all(const float* __restrict__ Wa, const float* __restrict__ Wb,
                const float* __restrict__ Wc, const float* __restrict__ Wd,
                const float* __restrict__ W1, const float* __restrict__ W2,
                __half* __restrict__ out)
{
    __shared__ float tile[32][33];
    int z = blockIdx.z;
    const float* W;
    __half* hT;
    int K, N, n0, k0;
    if (z < 4) {
        W = (z == 0) ? Wa : (z == 1) ? Wb : (z == 2) ? Wc : Wd;
        hT = out + (size_t)z * M1;
        K = DD; N = DD;
        if (blockIdx.x >= DD/32) return;
        n0 = blockIdx.x * 32; k0 = blockIdx.y * 32;
    } else if (z == 4) {
        W = W1; hT = out + 4*(size_t)M1;
        K = DD; N = FF;
        n0 = blockIdx.x * 32; k0 = blockIdx.y * 32;
    } else {
        W = W2; hT = out + 8*(size_t)M1;
        K = FF; N = DD;
        n0 = blockIdx.y * 32; k0 = blockIdx.x * 32;
    }
    int tx = threadIdx.x & 31, ty = threadIdx.x >> 5;
    for (int j = ty; j < 32; j += 8)
        tile[j][tx] = W[(size_t)(k0 + j) * N + n0 + tx];
    __syncthreads();
    for (int j = ty; j < 32; j += 8)
        hT[(size_t)(n0 + j) * K + k0 + tx] = __float2half_rn(tile[tx][j]);
}

// ---------------- single-pass fp16 GEMM: 256x128 tile, BK=64, 3-stage -----------
#define GSTR 72
#define A_PLANE (256*GSTR)
#define B_PLANE (128*GSTR)
#define F16_STG (A_PLANE + B_PLANE)
#define F16_SMEM (3*F16_STG*2)

__global__ __launch_bounds__(512, 1)
void gemm_f16(const __half* __restrict__ A, const __half* __restrict__ B,
              const float* __restrict__ bias, const float* __restrict__ res,
              float* __restrict__ outF, __half* __restrict__ out16,
              int M, int N, int K, int act, int qcols)
{
    extern __shared__ uint16_t sh[];
    uint32_t sb = s2u(sh);
    int tid = threadIdx.x;
    int wid = tid >> 5, lane = tid & 31;
    int g = lane >> 2, tg = lane & 3;
    int q8 = lane >> 3, e8 = lane & 7;
    int warp_m = wid & 3, warp_n = wid >> 2;
    int m0 = blockIdx.y * 256, n0 = blockIdx.x * 128;
    float cscale = (n0 < qcols) ? QSCALE : 1.f;

    float acc[4][4][4];
    #pragma unroll
    for (int mt = 0; mt < 4; mt++)
        #pragma unroll
        for (int nt = 0; nt < 4; nt++)
            #pragma unroll
            for (int c = 0; c < 4; c++) acc[mt][nt][c] = 0.f;

    const __half* gp[6];
    uint32_t so[6];
    #pragma unroll
    for (int u = 0; u < 6; u++) {
        int f = tid + u * 512;
        if (f < 2048) {
            int row = f >> 3, c = (f & 7) << 3;
            gp[u] = A + (size_t)(m0 + row) * K + c;
            so[u] = (uint32_t)(row * GSTR + c) * 2;
        } else {
            int fb = f - 2048;
            int row = fb >> 3, c = (fb & 7) << 3;
            gp[u] = B + (size_t)(n0 + row) * K + c;
            so[u] = (uint32_t)(A_PLANE + row * GSTR + c) * 2;
        }
    }
    const int T = K >> 6;

    auto issue = [&](int t) {
        uint32_t st = sb + (uint32_t)(t % 3) * (F16_STG * 2);
        int k0 = t << 6;
        #pragma unroll
        for (int u = 0; u < 6; u++) cp16(st + so[u], gp[u] + k0);
        cp_commit();
    };

    issue(0);
    issue(1);

    uint32_t aoff[4], boff[2];
    #pragma unroll
    for (int mt = 0; mt < 4; mt++)
        aoff[mt] = (uint32_t)((warp_m * 64 + mt * 16 + e8 + (q8 & 1) * 8) * GSTR
                              + (q8 >> 1) * 8);
    #pragma unroll
    for (int p = 0; p < 2; p++)
        boff[p] = (uint32_t)((warp_n * 32 + (2 * p + (q8 >> 1)) * 8 + e8) * GSTR
                             + (q8 & 1) * 8);

    for (int t = 0; t < T; t++) {
        if (t == T - 1) cp_wait0(); else cp_wait1();
        __syncthreads();
        if (t + 2 < T) issue(t + 2);

        uint32_t st = sb + (uint32_t)(t % 3) * (F16_STG * 2);
        #pragma unroll
        for (int ks = 0; ks < 64; ks += 16) {
            uint32_t af[4][4];
            #pragma unroll
            for (int mt = 0; mt < 4; mt++)
                ldm4(st + (aoff[mt] + ks) * 2,
                     af[mt][0], af[mt][1], af[mt][2], af[mt][3]);
            #pragma unroll
            for (int p = 0; p < 2; p++) {
                uint32_t b0, b1, b2, b3;
                ldm4(st + (A_PLANE + boff[p] + ks) * 2, b0, b1, b2, b3);
                int ntA = 2 * p, ntB = ntA + 1;
                #pragma unroll
                for (int mt = 0; mt < 4; mt++) {
                    hmma16(acc[mt][ntA], af[mt][0], af[mt][1], af[mt][2], af[mt][3], b0, b1);
                    hmma16(acc[mt][ntB], af[mt][0], af[mt][1], af[mt][2], af[mt][3], b2, b3);
                }
            }
        }
    }

    #pragma unroll
    for (int mt = 0; mt < 4; mt++) {
        #pragma unroll
        for (int nt = 0; nt < 4; nt++) {
            int row = m0 + warp_m * 64 + mt * 16 + g;
            int col = n0 + warp_n * 32 + nt * 8 + 2 * tg;
            #pragma unroll
            for (int half = 0; half < 2; half++) {
                int r = row + half * 8;
                float v0 = acc[mt][nt][half * 2 + 0];
                float v1 = acc[mt][nt][half * 2 + 1];
                if (bias) { v0 += bias[col]; v1 += bias[col + 1]; }
                if (act) {
                    v0 = v0 / (1.f + __expf(-v0));
                    v1 = v1 / (1.f + __expf(-v1));
                }
                v0 *= cscale; v1 *= cscale;
                size_t o = (size_t)r * N + col;
                if (outF) {
                    if (res) {
                        float2 rv = *reinterpret_cast<const float2*>(res + o);
                        v0 += rv.x; v1 += rv.y;
                    }
                    *reinterpret_cast<float2*>(outF + o) = make_float2(v0, v1);
                } else {
                    *reinterpret_cast<uint32_t*>(out16 + o) = pk16(v0, v1);
                }
            }
        }
    }
}

// ---------------- fp16 flash attention: 64-key tiles, 3-stage, 1 sync/tile ------
#define AT_STRIDE 72
#define QPB (128*AT_STRIDE*2)
#define KPB (64*AT_STRIDE*2)
#define KV_STG_B (2*KPB)
#define KV_BASE QPB
#define AT_SMEM_BYTES (KV_BASE + 3*KV_STG_B + 3*64*4)

__global__ __launch_bounds__(256, 2)
void attn_tc(const __half* __restrict__ qkv, const int* __restrict__ amask,
             __half* __restrict__ ctx16)
{
    extern __shared__ uint16_t ash[];
    uint32_t sb = s2u(ash);
    float* koff = reinterpret_cast<float*>((char*)ash + KV_BASE + 3 * KV_STG_B);

    int tid = threadIdx.x;
    int lane = tid & 31, w = tid >> 5;
    int g = lane >> 2, tg = lane & 3;
    int q8 = lane >> 3, e8 = lane & 7;
    int bh = blockIdx.y;
    int b = bh >> 4, h = bh & 15;
    int qt = gridDim.x - 1 - blockIdx.x;
    int q0 = qt * 128;
    const size_t rowbase = (size_t)b * SS;
    const int hoff = h * 64;
    const int ktmax = 2 * qt + 1;

    const __half* qgp[4]; uint32_t qso[4];
    #pragma unroll
    for (int u = 0; u < 4; u++) {
        int f = tid + u * 256;
        int row = f >> 3, c = (f & 7) << 3;
        qgp[u] = qkv + (rowbase + q0 + row) * QKVD + hoff + c;
        qso[u] = (uint32_t)(row * AT_STRIDE + c) * 2;
    }
    const __half* kvgp[4]; uint32_t kvso[4]; int kvrow[4];
    #pragma unroll
    for (int u = 0; u < 4; u++) {
        int f = tid + u * 256;
        int plane = f >> 9, fr = f & 511;
        int row = fr >> 3, c = (fr & 7) << 3;
        kvgp[u] = qkv + (plane ? 2 * DD : DD) + rowbase * QKVD + hoff + c;
        kvrow[u] = row;
        kvso[u] = (uint32_t)KV_BASE + (uint32_t)(plane * (KPB / 2) + row * AT_STRIDE + c) * 2;
    }

    auto issueKV = [&](int kt) {
        uint32_t st = sb + (uint32_t)(kt % 3) * KV_STG_B;
        int k0 = kt * 64;
        #pragma unroll
        for (int u = 0; u < 4; u++)
            cp16(st + kvso[u], kvgp[u] + (size_t)(k0 + kvrow[u]) * QKVD);
        cp_commit();
        if (tid < 64)
            koff[(kt % 3) * 64 + tid] = (amask[b * SS + k0 + tid] == 1) ? 0.f : NEGBIG;
    };

    #pragma unroll
    for (int u = 0; u < 4; u++) cp16(sb + qso[u], qgp[u]);
    cp_commit();
    issueKV(0);
    issueKV(1);
    cp_wait1();
    __syncthreads();

    uint32_t qf[4][4];
    uint32_t qoffb = (uint32_t)((w * 16 + e8 + (q8 & 1) * 8) * AT_STRIDE + (q8 >> 1) * 8);
    #pragma unroll
    for (int kt = 0; kt < 4; kt++)
        ldm4(sb + (qoffb + 16 * kt) * 2, qf[kt][0], qf[kt][1], qf[kt][2], qf[kt][3]);

    uint32_t kboff[4], vboff[4];
    #pragma unroll
    for (int p = 0; p < 4; p++) {
        kboff[p] = (uint32_t)(((2 * p + (q8 >> 1)) * 8 + e8) * AT_STRIDE + (q8 & 1) * 8);
        vboff[p] = (uint32_t)(((q8 & 1) * 8 + e8) * AT_STRIDE + (2 * p + (q8 >> 1)) * 8);
    }

    float o[8][4];
    #pragma unroll
    for (int nt = 0; nt < 8; nt++)
        #pragma unroll
        for (int c = 0; c < 4; c++) o[nt][c] = 0.f;
    float m0v = NEGBIG, m1v = NEGBIG, l0 = 0.f, l1 = 0.f;
    int r0g = q0 + w * 16 + g, r1g = r0g + 8;

    for (int kt_g = 0; kt_g <= ktmax; kt_g++) {
        int k0 = kt_g * 64;
        if (kt_g > 0) {
            if (kt_g == ktmax) cp_wait0(); else cp_wait1();
            __syncthreads();
        }
        if (kt_g + 2 <= ktmax) issueKV(kt_g + 2);

        uint32_t stK = sb + KV_BASE + (uint32_t)(kt_g % 3) * KV_STG_B;
        uint32_t stV = stK + KPB;
        const float* kofft = koff + (kt_g % 3) * 64;

        float s[8][4];
        #pragma unroll
        for (int nt = 0; nt < 8; nt++)
            #pragma unroll
            for (int c = 0; c < 4; c++) s[nt][c] = 0.f;
        #pragma unroll
        for (int kt = 0; kt < 4; kt++) {
            #pragma unroll
            for (int p = 0; p < 4; p++) {
                uint32_t b0, b1, b2, b3;
                ldm4(stK + (kboff[p] + 16 * kt) * 2, b0, b1, b2, b3);
                int ntA = 2 * p, ntB = ntA + 1;
                hmma16(s[ntA], qf[kt][0], qf[kt][1], qf[kt][2], qf[kt][3], b0, b1);
                hmma16(s[ntB], qf[kt][0], qf[kt][1], qf[kt][2], qf[kt][3], b2, b3);
            }
        }

        float mx0 = NEGBIG, mx1 = NEGBIG;
        if (kt_g >= 2 * qt) {
            #pragma unroll
            for (int nt = 0; nt < 8; nt++) {
                int c0 = k0 + 8 * nt + 2 * tg;
                float kf0 = kofft[8 * nt + 2 * tg], kf1 = kofft[8 * nt + 2 * tg + 1];
                float v0 = s[nt][0] + kf0;
                float v1 = s[nt][1] + kf1;
                float v2 = s[nt][2] + kf0;
                float v3 = s[nt][3] + kf1;
                if (c0     > r0g) v0 = NEGBIG;
                if (c0 + 1 > r0g) v1 = NEGBIG;
                if (c0     > r1g) v2 = NEGBIG;
                if (c0 + 1 > r1g) v3 = NEGBIG;
                s[nt][0] = v0; s[nt][1] = v1; s[nt][2] = v2; s[nt][3] = v3;
                mx0 = fmaxf(mx0, fmaxf(v0, v1));
                mx1 = fmaxf(mx1, fmaxf(v2, v3));
            }
        } else {
            #pragma unroll
            for (int nt = 0; nt < 8; nt++) {
                float kf0 = kofft[8 * nt + 2 * tg], kf1 = kofft[8 * nt + 2 * tg + 1];
                float v0 = s[nt][0] + kf0;
                float v1 = s[nt][1] + kf1;
                float v2 = s[nt][2] + kf0;
                float v3 = s[nt][3] + kf1;
                s[nt][0] = v0; s[nt][1] = v1; s[nt][2] = v2; s[nt][3] = v3;
                mx0 = fmaxf(mx0, fmaxf(v0, v1));
                mx1 = fmaxf(mx1, fmaxf(v2, v3));
            }
        }
        mx0 = fmaxf(mx0, __shfl_xor_sync(0xffffffffu, mx0, 1));
        mx0 = fmaxf(mx0, __shfl_xor_sync(0xffffffffu, mx0, 2));
        mx1 = fmaxf(mx1, __shfl_xor_sync(0xffffffffu, mx1, 1));
        mx1 = fmaxf(mx1, __shfl_xor_sync(0xffffffffu, mx1, 2));

        float mn0 = fmaxf(m0v, mx0), mn1 = fmaxf(m1v, mx1);
        float al0 = ex2f(m0v - mn0), al1 = ex2f(m1v - mn1);
        m0v = mn0; m1v = mn1;
        l0 *= al0; l1 *= al1;

        #pragma unroll
        for (int nt = 0; nt < 8; nt++) {
            float p0 = ex2f(s[nt][0] - m0v);
            float p1 = ex2f(s[nt][1] - m0v);
            float p2 = ex2f(s[nt][2] - m1v);
            float p3 = ex2f(s[nt][3] - m1v);
            s[nt][0] = p0; s[nt][1] = p1; s[nt][2] = p2; s[nt][3] = p3;
            l0 += p0 + p1; l1 += p2 + p3;
        }
        #pragma unroll
        for (int nt = 0; nt < 8; nt++) {
            o[nt][0] *= al0; o[nt][1] *= al0;
            o[nt][2] *= al1; o[nt][3] *= al1;
        }

        #pragma unroll
        for (int ktP = 0; ktP < 4; ktP++) {
            int ntA = 2 * ktP, ntB = ntA + 1;
            uint32_t a0 = pk16(s[ntA][0], s[ntA][1]);
            uint32_t a1 = pk16(s[ntA][2], s[ntA][3]);
            uint32_t a2 = pk16(s[ntB][0], s[ntB][1]);
            uint32_t a3 = pk16(s[ntB][2], s[ntB][3]);
            #pragma unroll
            for (int p = 0; p < 4; p++) {
                uint32_t v0, v1, v2, v3;
                ldm4t(stV + (vboff[p] + 16 * ktP * AT_STRIDE) * 2, v0, v1, v2, v3);
                int n2A = 2 * p, n2B = n2A + 1;
                hmma16(o[n2A], a0, a1, a2, a3, v0, v1);
                hmma16(o[n2B], a0, a1, a2, a3, v2, v3);
            }
        }
    }

    l0 += __shfl_xor_sync(0xffffffffu, l0, 1);
    l0 += __shfl_xor_sync(0xffffffffu, l0, 2);
    l1 += __shfl_xor_sync(0xffffffffu, l1, 1);
    l1 += __shfl_xor_sync(0xffffffffu, l1, 2);
    float inv0 = 1.f / l0, inv1 = 1.f / l1;

    #pragma unroll
    for (int nt = 0; nt < 8; nt++) {
        int col = hoff + 8 * nt + 2 * tg;
        *reinterpret_cast<uint32_t*>(ctx16 + (rowbase + r0g) * DD + col) =
            pk16(o[nt][0] * inv0, o[nt][1] * inv0);
        *reinterpret_cast<uint32_t*>(ctx16 + (rowbase + r1g) * DD + col) =
            pk16(o[nt][2] * inv1, o[nt][3] * inv1);
    }
}

// ---------------- host ---------------------------------------------------------
extern "C" void kernel_launch(void* const* d_in, const int* in_sizes, int n_in,
                              void* d_out, int out_size)
{
    const float* hidden = (const float*)d_in[0];
    const int*   amask  = (const int*)  d_in[1];
    const float* Wq     = (const float*)d_in[2];
    const float* Wk     = (const float*)d_in[3];
    const float* Wv     = (const float*)d_in[4];
    const float* Wo     = (const float*)d_in[5];
    const float* ln1g   = (const float*)d_in[6];
    const float* ln1b   = (const float*)d_in[7];
    const float* W1     = (const float*)d_in[8];
    const float* b1     = (const float*)d_in[9];
    const float* W2     = (const float*)d_in[10];
    const float* b2     = (const float*)d_in[11];
    const float* ln2g   = (const float*)d_in[12];
    const float* ln2b   = (const float*)d_in[13];
    float* out = (float*)d_out;

    __half *x16, *qkv16, *ctx16, *y16, *h16, *w16;
    float* x2;
    cudaGetSymbolAddress((void**)&x16,   g_x16);
    cudaGetSymbolAddress((void**)&qkv16, g_qkv16);
    cudaGetSymbolAddress((void**)&ctx16, g_ctx16);
    cudaGetSymbolAddress((void**)&x2,    g_x2);
    cudaGetSymbolAddress((void**)&y16,   g_y16);
    cudaGetSymbolAddress((void**)&h16,   g_h16);
    cudaGetSymbolAddress((void**)&w16,   g_w16);

    cudaFuncSetAttribute(attn_tc, cudaFuncAttributeMaxDynamicSharedMemorySize,
                         AT_SMEM_BYTES);
    cudaFuncSetAttribute(gemm_f16, cudaFuncAttributeMaxDynamicSharedMemorySize,
                         F16_SMEM);

    const int M = MROWS;

    // all weight transposes in one launch
    trans16all<<<dim3(FF/32, DD/32, 6), 256>>>(Wq, Wk, Wv, Wo, W1, W2, w16);

    // LN1 -> fp16
    ln_f16<<<M, 256>>>(hidden, ln1g, ln1b, x16);
    // fused QKV projection -> fp16 (Q columns pre-scaled by 0.125*log2e)
    gemm_f16<<<dim3(QKVD/128, M/256), 512, F16_SMEM>>>(
        x16, w16, nullptr, nullptr, nullptr, qkv16, M, QKVD, DD, 0, DD);
    // attention -> ctx fp16
    attn_tc<<<dim3(SS/128, BB*HH), 256, AT_SMEM_BYTES>>>(qkv16, amask, ctx16);
    // output projection + residual -> fp32 x2
    gemm_f16<<<dim3(DD/128, M/256), 512, F16_SMEM>>>(
        ctx16, w16 + 3*(size_t)M1, nullptr, hidden, x2, nullptr, M, DD, DD, 0, 0);
    // LN2 -> fp16
    ln_f16<<<M, 256>>>(x2, ln2g, ln2b, y16);
    // FFN1 (bias + SiLU) -> fp16 h
    gemm_f16<<<dim3(FF/128, M/256), 512, F16_SMEM>>>(
        y16, w16 + 4*(size_t)M1, b1, nullptr, nullptr, h16, M, FF, DD, 1, 0);
    // FFN2 (bias + residual x2) -> fp32 out
    gemm_f16<<<dim3(DD/128, M/256), 512, F16_SMEM>>>(
        h16, w16 + 8*(size_t)M1, b2, x2, out, nullptr, M, DD, FF, 0, 0);
}

// round 16
// speedup vs baseline: 1.0160x; 1.0160x over previous
#include <cuda_runtime.h>
#include <cuda_fp16.h>
#include <math.h>
#include <stdint.h>

#define BB 4
#define SS 2048
#define DD 1024
#define FF 4096
#define HH 16
#define QKVD (3*DD)
#define NEGBIG -1e30f
#define MROWS (BB*SS)
#define M1 (DD*DD)
// 0.125 * log2(e) folded into Q
#define QSCALE 0.1803368801111204f

// ---------------- scratch ------------------------------------------------------
__device__ __half g_x16 [MROWS*DD];
__device__ __half g_qkv16[(size_t)MROWS*QKVD];
__device__ __half g_ctx16[MROWS*DD];
__device__ float  g_x2  [MROWS*DD];
__device__ __half g_y16 [MROWS*DD];
__device__ __half g_h16 [(size_t)MROWS*FF];
__device__ __half g_w16[(size_t)12*M1];

// ---------------- helpers ------------------------------------------------------
__device__ __forceinline__ uint32_t pk16(float a, float b) {
    __half2 h = __floats2half2_rn(a, b);
    return *reinterpret_cast<uint32_t*>(&h);
}
__device__ __forceinline__ float ex2f(float x) {
    float r;
    asm("ex2.approx.f32 %0, %1;" : "=f"(r) : "f"(x));
    return r;
}
__device__ __forceinline__ void hmma16(float* d, uint32_t a0, uint32_t a1,
                                       uint32_t a2, uint32_t a3,
                                       uint32_t b0, uint32_t b1) {
    asm volatile("mma.sync.aligned.m16n8k16.row.col.f32.f16.f16.f32 "
                 "{%0,%1,%2,%3}, {%4,%5,%6,%7}, {%8,%9}, {%0,%1,%2,%3};"
                 : "+f"(d[0]), "+f"(d[1]), "+f"(d[2]), "+f"(d[3])
                 : "r"(a0), "r"(a1), "r"(a2), "r"(a3), "r"(b0), "r"(b1));
}
__device__ __forceinline__ uint32_t s2u(const void* p) {
    return (uint32_t)__cvta_generic_to_shared(p);
}
__device__ __forceinline__ void cp16(uint32_t dst, const void* src) {
    asm volatile("cp.async.ca.shared.global [%0], [%1], 16;" :: "r"(dst), "l"(src));
}
__device__ __forceinline__ void cp_commit() { asm volatile("cp.async.commit_group;"); }
__device__ __forceinline__ void cp_wait0()  { asm volatile("cp.async.wait_group 0;"); }
__device__ __forceinline__ void cp_wait1()  { asm volatile("cp.async.wait_group 1;"); }
__device__ __forceinline__ void ldm4(uint32_t addr, uint32_t& r0, uint32_t& r1,
                                     uint32_t& r2, uint32_t& r3) {
    asm volatile("ldmatrix.sync.aligned.m8n8.x4.shared.b16 {%0,%1,%2,%3}, [%4];"
                 : "=r"(r0), "=r"(r1), "=r"(r2), "=r"(r3) : "r"(addr));
}
__device__ __forceinline__ void ldm4t(uint32_t addr, uint32_t& r0, uint32_t& r1,
                                      uint32_t& r2, uint32_t& r3) {
    asm volatile("ldmatrix.sync.aligned.m8n8.x4.trans.shared.b16 {%0,%1,%2,%3}, [%4];"
                 : "=r"(r0), "=r"(r1), "=r"(r2), "=r"(r3) : "r"(addr));
}

// ---------------- LayerNorm -> single fp16 -------------------------------------
__global__ __launch_bounds__(256)
void ln_f16(const float* __restrict__ x, const float* __restrict__ g,
            const float* __restrict__ b, __half* __restrict__ out16)
{
    int row = blockIdx.x;
    int tid = threadIdx.x;
    const float* xr = x + (size_t)row * DD;
    float4 v = *reinterpret_cast<const float4*>(xr + tid * 4);
    float s  = v.x + v.y + v.z + v.w;
    float sq = v.x*v.x + v.y*v.y + v.z*v.z + v.w*v.w;
    #pragma unroll
    for (int o = 16; o > 0; o >>= 1) {
        s  += __shfl_xor_sync(0xffffffffu, s,  o);
        sq += __shfl_xor_sync(0xffffffffu, sq, o);
    }
    __shared__ float ws[8], wq[8];
    __shared__ float smean, srstd;
    int wid = tid >> 5, lane = tid & 31;
    if (lane == 0) { ws[wid] = s; wq[wid] = sq; }
    __syncthreads();
    if (tid == 0) {
        float S = 0.f, Q = 0.f;
        #pragma unroll
        for (int i = 0; i < 8; i++) { S += ws[i]; Q += wq[i]; }
        float mean = S * (1.f / DD);
        float var  = fmaxf(Q * (1.f / DD) - mean * mean, 0.f);
        smean = mean;
        srstd = rsqrtf(var + 1e-12f);
    }
    __syncthreads();
    float mean = smean, rstd = srstd;
    float4 gv = *reinterpret_cast<const float4*>(g + tid * 4);
    float4 bv = *reinterpret_cast<const float4*>(b + tid * 4);
    uint2 pk = make_uint2(
        pk16((v.x - mean) * rstd * gv.x + bv.x, (v.y - mean) * rstd * gv.y + bv.y),
        pk16((v.z - mean) * rstd * gv.z + bv.z, (v.w - mean) * rstd * gv.w + bv.w));
    *reinterpret_cast<uint2*>(out16 + (size_t)row * DD + tid * 4) = pk;
}

// ---------------- batched weight transpose -> fp16 ------------------------------
__global__ __launch_bounds__(256)
void trans16all(const float* __restrict__ Wa, const float* __restrict__ Wb,
                const float* __restrict__ Wc, const float* __restrict__ Wd,
                const float* __restrict__ W1, const float* __restrict__ W2,
                __half* __restrict__ out)
{
    __shared__ float tile[32][33];
    int z = blockIdx.z;
    const float* W;
    __half* hT;
    int K, N, n0, k0;
    if (z < 4) {
        if (blockIdx.x >= DD/32) return;
        W = (z == 0) ? Wa : (z == 1) ? Wb : (z == 2) ? Wc : Wd;
        hT = out + (size_t)z * M1;
        K = DD; N = DD;
        n0 = blockIdx.x * 32; k0 = blockIdx.y * 32;
    } else if (z == 4) {
        W = W1; hT = out + 4*(size_t)M1;
        K = DD; N = FF;
        n0 = blockIdx.x * 32; k0 = blockIdx.y * 32;
    } else {
        W = W2; hT = out + 8*(size_t)M1;
        K = FF; N = DD;
        n0 = blockIdx.y * 32; k0 = blockIdx.x * 32;
    }
    int tx = threadIdx.x & 31, ty = threadIdx.x >> 5;
    for (int j = ty; j < 32; j += 8)
        tile[j][tx] = W[(size_t)(k0 + j) * N + n0 + tx];
    __syncthreads();
    for (int j = ty; j < 32; j += 8)
        hT[(size_t)(n0 + j) * K + k0 + tx] = __float2half_rn(tile[tx][j]);
}

// ---------------- single-pass fp16 GEMM: 256x128 tile, BK=64, 2-stage -----------
#define GSTR 72
#define A_PLANE (256*GSTR)
#define B_PLANE (128*GSTR)
#define F16_STG (A_PLANE + B_PLANE)
#define F16_SMEM (2*F16_STG*2)

__global__ __launch_bounds__(512, 1)
void gemm_f16(const __half* __restrict__ A, const __half* __restrict__ B,
              const float* __restrict__ bias, const float* __restrict__ res,
              float* __restrict__ outF, __half* __restrict__ out16,
              int M, int N, int K, int act, int qcols)
{
    extern __shared__ uint16_t sh[];
    uint32_t sb = s2u(sh);
    int tid = threadIdx.x;
    int wid = tid >> 5, lane = tid & 31;
    int g = lane >> 2, tg = lane & 3;
    int q8 = lane >> 3, e8 = lane & 7;
    int warp_m = wid & 3, warp_n = wid >> 2;
    int m0 = blockIdx.y * 256, n0 = blockIdx.x * 128;
    float cscale = (n0 < qcols) ? QSCALE : 1.f;

    float acc[4][4][4];
    #pragma unroll
    for (int mt = 0; mt < 4; mt++)
        #pragma unroll
        for (int nt = 0; nt < 4; nt++)
            #pragma unroll
            for (int c = 0; c < 4; c++) acc[mt][nt][c] = 0.f;

    const __half* gp[6];
    uint32_t so[6];
    #pragma unroll
    for (int u = 0; u < 6; u++) {
        int f = tid + u * 512;
        if (f < 2048) {
            int row = f >> 3, c = (f & 7) << 3;
            gp[u] = A + (size_t)(m0 + row) * K + c;
            so[u] = (uint32_t)(row * GSTR + c) * 2;
        } else {
            int fb = f - 2048;
            int row = fb >> 3, c = (fb & 7) << 3;
            gp[u] = B + (size_t)(n0 + row) * K + c;
            so[u] = (uint32_t)(A_PLANE + row * GSTR + c) * 2;
        }
    }
    const int T = K >> 6;

    auto issue = [&](int t) {
        uint32_t st = sb + (uint32_t)(t & 1) * (F16_STG * 2);
        int k0 = t << 6;
        #pragma unroll
        for (int u = 0; u < 6; u++) cp16(st + so[u], gp[u] + k0);
        cp_commit();
    };

    issue(0);

    uint32_t aoff[4], boff[2];
    #pragma unroll
    for (int mt = 0; mt < 4; mt++)
        aoff[mt] = (uint32_t)((warp_m * 64 + mt * 16 + e8 + (q8 & 1) * 8) * GSTR
                              + (q8 >> 1) * 8);
    #pragma unroll
    for (int p = 0; p < 2; p++)
        boff[p] = (uint32_t)((warp_n * 32 + (2 * p + (q8 >> 1)) * 8 + e8) * GSTR
                             + (q8 & 1) * 8);

    for (int t = 0; t < T; t++) {
        cp_wait0();
        __syncthreads();
        if (t + 1 < T) issue(t + 1);

        uint32_t st = sb + (uint32_t)(t & 1) * (F16_STG * 2);
        #pragma unroll
        for (int ks = 0; ks < 64; ks += 16) {
            uint32_t af[4][4];
            #pragma unroll
            for (int mt = 0; mt < 4; mt++)
                ldm4(st + (aoff[mt] + ks) * 2,
                     af[mt][0], af[mt][1], af[mt][2], af[mt][3]);
            #pragma unroll
            for (int p = 0; p < 2; p++) {
                uint32_t b0, b1, b2, b3;
                ldm4(st + (A_PLANE + boff[p] + ks) * 2, b0, b1, b2, b3);
                int ntA = 2 * p, ntB = ntA + 1;
                #pragma unroll
                for (int mt = 0; mt < 4; mt++) {
                    hmma16(acc[mt][ntA], af[mt][0], af[mt][1], af[mt][2], af[mt][3], b0, b1);
                    hmma16(acc[mt][ntB], af[mt][0], af[mt][1], af[mt][2], af[mt][3], b2, b3);
                }
            }
        }
    }

    #pragma unroll
    for (int mt = 0; mt < 4; mt++) {
        #pragma unroll
        for (int nt = 0; nt < 4; nt++) {
            int row = m0 + warp_m * 64 + mt * 16 + g;
            int col = n0 + warp_n * 32 + nt * 8 + 2 * tg;
            #pragma unroll
            for (int half = 0; half < 2; half++) {
                int r = row + half * 8;
                float v0 = acc[mt][nt][half * 2 + 0];
                float v1 = acc[mt][nt][half * 2 + 1];
                if (bias) { v0 += bias[col]; v1 += bias[col + 1]; }
                if (act) {
                    v0 = v0 / (1.f + __expf(-v0));
                    v1 = v1 / (1.f + __expf(-v1));
                }
                v0 *= cscale; v1 *= cscale;
                size_t o = (size_t)r * N + col;
                if (outF) {
                    if (res) {
                        float2 rv = *reinterpret_cast<const float2*>(res + o);
                        v0 += rv.x; v1 += rv.y;
                    }
                    *reinterpret_cast<float2*>(outF + o) = make_float2(v0, v1);
                } else {
                    *reinterpret_cast<uint32_t*>(out16 + o) = pk16(v0, v1);
                }
            }
        }
    }
}

// ---------------- fp16 flash attention: 64-key tiles, 3-stage, 1 sync/tile ------
#define AT_STRIDE 72
#define QPB (128*AT_STRIDE*2)
#define KPB (64*AT_STRIDE*2)
#define KV_STG_B (2*KPB)
#define KV_BASE QPB
#define AT_SMEM_BYTES (KV_BASE + 3*KV_STG_B + 3*64*4)

__global__ __launch_bounds__(256, 2)
void attn_tc(const __half* __restrict__ qkv, const int* __restrict__ amask,
             __half* __restrict__ ctx16)
{
    extern __shared__ uint16_t ash[];
    uint32_t sb = s2u(ash);
    float* koff = reinterpret_cast<float*>((char*)ash + KV_BASE + 3 * KV_STG_B);

    int tid = threadIdx.x;
    int lane = tid & 31, w = tid >> 5;
    int g = lane >> 2, tg = lane & 3;
    int q8 = lane >> 3, e8 = lane & 7;
    int bh = blockIdx.y;
    int b = bh >> 4, h = bh & 15;
    int qt = gridDim.x - 1 - blockIdx.x;
    int q0 = qt * 128;
    const size_t rowbase = (size_t)b * SS;
    const int hoff = h * 64;
    const int ktmax = 2 * qt + 1;

    const __half* qgp[4]; uint32_t qso[4];
    #pragma unroll
    for (int u = 0; u < 4; u++) {
        int f = tid + u * 256;
        int row = f >> 3, c = (f & 7) << 3;
        qgp[u] = qkv + (rowbase + q0 + row) * QKVD + hoff + c;
        qso[u] = (uint32_t)(row * AT_STRIDE + c) * 2;
    }
    const __half* kvgp[4]; uint32_t kvso[4]; int kvrow[4];
    #pragma unroll
    for (int u = 0; u < 4; u++) {
        int f = tid + u * 256;
        int plane = f >> 9, fr = f & 511;
        int row = fr >> 3, c = (fr & 7) << 3;
        kvgp[u] = qkv + (plane ? 2 * DD : DD) + rowbase * QKVD + hoff + c;
        kvrow[u] = row;
        kvso[u] = (uint32_t)KV_BASE + (uint32_t)(plane * (KPB / 2) + row * AT_STRIDE + c) * 2;
    }

    auto issueKV = [&](int kt) {
        uint32_t st = sb + (uint32_t)(kt % 3) * KV_STG_B;
        int k0 = kt * 64;
        #pragma unroll
        for (int u = 0; u < 4; u++)
            cp16(st + kvso[u], kvgp[u] + (size_t)(k0 + kvrow[u]) * QKVD);
        cp_commit();
        if (tid < 64)
            koff[(kt % 3) * 64 + tid] = (amask[b * SS + k0 + tid] == 1) ? 0.f : NEGBIG;
    };

    #pragma unroll
    for (int u = 0; u < 4; u++) cp16(sb + qso[u], qgp[u]);
    cp_commit();
    issueKV(0);
    issueKV(1);
    cp_wait1();
    __syncthreads();

    uint32_t qf[4][4];
    uint32_t qoffb = (uint32_t)((w * 16 + e8 + (q8 & 1) * 8) * AT_STRIDE + (q8 >> 1) * 8);
    #pragma unroll
    for (int kt = 0; kt < 4; kt++)
        ldm4(sb + (qoffb + 16 * kt) * 2, qf[kt][0], qf[kt][1], qf[kt][2], qf[kt][3]);

    uint32_t kboff[4], vboff[4];
    #pragma unroll
    for (int p = 0; p < 4; p++) {
        kboff[p] = (uint32_t)(((2 * p + (q8 >> 1)) * 8 + e8) * AT_STRIDE + (q8 & 1) * 8);
        vboff[p] = (uint32_t)(((q8 & 1) * 8 + e8) * AT_STRIDE + (2 * p + (q8 >> 1)) * 8);
    }

    float o[8][4];
    #pragma unroll
    for (int nt = 0; nt < 8; nt++)
        #pragma unroll
        for (int c = 0; c < 4; c++) o[nt][c] = 0.f;
    float m0v = NEGBIG, m1v = NEGBIG, l0 = 0.f, l1 = 0.f;
    int r0g = q0 + w * 16 + g, r1g = r0g + 8;

    for (int kt_g = 0; kt_g <= ktmax; kt_g++) {
        int k0 = kt_g * 64;
        if (kt_g > 0) {
            if (kt_g == ktmax) cp_wait0(); else cp_wait1();
            __syncthreads();
        }
        if (kt_g + 2 <= ktmax) issueKV(kt_g + 2);

        uint32_t stK = sb + KV_BASE + (uint32_t)(kt_g % 3) * KV_STG_B;
        uint32_t stV = stK + KPB;
        const float* kofft = koff + (kt_g % 3) * 64;

        float s[8][4];
        #pragma unroll
        for (int nt = 0; nt < 8; nt++)
            #pragma unroll
            for (int c = 0; c < 4; c++) s[nt][c] = 0.f;
        #pragma unroll
        for (int kt = 0; kt < 4; kt++) {
            #pragma unroll
            for (int p = 0; p < 4; p++) {
                uint32_t b0, b1, b2, b3;
                ldm4(stK + (kboff[p] + 16 * kt) * 2, b0, b1, b2, b3);
                int ntA = 2 * p, ntB = ntA + 1;
                hmma16(s[ntA], qf[kt][0], qf[kt][1], qf[kt][2], qf[kt][3], b0, b1);
                hmma16(s[ntB], qf[kt][0], qf[kt][1], qf[kt][2], qf[kt][3], b2, b3);
            }
        }

        float mx0 = NEGBIG, mx1 = NEGBIG;
        if (kt_g >= 2 * qt) {
            #pragma unroll
            for (int nt = 0; nt < 8; nt++) {
                int c0 = k0 + 8 * nt + 2 * tg;
                float kf0 = kofft[8 * nt + 2 * tg], kf1 = kofft[8 * nt + 2 * tg + 1];
                float v0 = s[nt][0] + kf0;
                float v1 = s[nt][1] + kf1;
                float v2 = s[nt][2] + kf0;
                float v3 = s[nt][3] + kf1;
                if (c0     > r0g) v0 = NEGBIG;
                if (c0 + 1 > r0g) v1 = NEGBIG;
                if (c0     > r1g) v2 = NEGBIG;
                if (c0 + 1 > r1g) v3 = NEGBIG;
                s[nt][0] = v0; s[nt][1] = v1; s[nt][2] = v2; s[nt][3] = v3;
                mx0 = fmaxf(mx0, fmaxf(v0, v1));
                mx1 = fmaxf(mx1, fmaxf(v2, v3));
            }
        } else {
            #pragma unroll
            for (int nt = 0; nt < 8; nt++) {
                float kf0 = kofft[8 * nt + 2 * tg], kf1 = kofft[8 * nt + 2 * tg + 1];
                float v0 = s[nt][0] + kf0;
                float v1 = s[nt][1] + kf1;
                float v2 = s[nt][2] + kf0;
                float v3 = s[nt][3] + kf1;
                s[nt][0] = v0; s[nt][1] = v1; s[nt][2] = v2; s[nt][3] = v3;
                mx0 = fmaxf(mx0, fmaxf(v0, v1));
                mx1 = fmaxf(mx1, fmaxf(v2, v3));
            }
        }
        mx0 = fmaxf(mx0, __shfl_xor_sync(0xffffffffu, mx0, 1));
        mx0 = fmaxf(mx0, __shfl_xor_sync(0xffffffffu, mx0, 2));
        mx1 = fmaxf(mx1, __shfl_xor_sync(0xffffffffu, mx1, 1));
        mx1 = fmaxf(mx1, __shfl_xor_sync(0xffffffffu, mx1, 2));

        float mn0 = fmaxf(m0v, mx0), mn1 = fmaxf(m1v, mx1);
        float al0 = ex2f(m0v - mn0), al1 = ex2f(m1v - mn1);
        m0v = mn0; m1v = mn1;
        l0 *= al0; l1 *= al1;

        #pragma unroll
        for (int nt = 0; nt < 8; nt++) {
            float p0 = ex2f(s[nt][0] - m0v);
            float p1 = ex2f(s[nt][1] - m0v);
            float p2 = ex2f(s[nt][2] - m1v);
            float p3 = ex2f(s[nt][3] - m1v);
            s[nt][0] = p0; s[nt][1] = p1; s[nt][2] = p2; s[nt][3] = p3;
            l0 += p0 + p1; l1 += p2 + p3;
        }
        #pragma unroll
        for (int nt = 0; nt < 8; nt++) {
            o[nt][0] *= al0; o[nt][1] *= al0;
            o[nt][2] *= al1; o[nt][3] *= al1;
        }

        #pragma unroll
        for (int ktP = 0; ktP < 4; ktP++) {
            int ntA = 2 * ktP, ntB = ntA + 1;
            uint32_t a0 = pk16(s[ntA][0], s[ntA][1]);
            uint32_t a1 = pk16(s[ntA][2], s[ntA][3]);
            uint32_t a2 = pk16(s[ntB][0], s[ntB][1]);
            uint32_t a3 = pk16(s[ntB][2], s[ntB][3]);
            #pragma unroll
            for (int p = 0; p < 4; p++) {
                uint32_t v0, v1, v2, v3;
                ldm4t(stV + (vboff[p] + 16 * ktP * AT_STRIDE) * 2, v0, v1, v2, v3);
                int n2A = 2 * p, n2B = n2A + 1;
                hmma16(o[n2A], a0, a1, a2, a3, v0, v1);
                hmma16(o[n2B], a0, a1, a2, a3, v2, v3);
            }
        }
    }

    l0 += __shfl_xor_sync(0xffffffffu, l0, 1);
    l0 += __shfl_xor_sync(0xffffffffu, l0, 2);
    l1 += __shfl_xor_sync(0xffffffffu, l1, 1);
    l1 += __shfl_xor_sync(0xffffffffu, l1, 2);
    float inv0 = 1.f / l0, inv1 = 1.f / l1;

    #pragma unroll
    for (int nt = 0; nt < 8; nt++) {
        int col = hoff + 8 * nt + 2 * tg;
        *reinterpret_cast<uint32_t*>(ctx16 + (rowbase + r0g) * DD + col) =
            pk16(o[nt][0] * inv0, o[nt][1] * inv0);
        *reinterpret_cast<uint32_t*>(ctx16 + (rowbase + r1g) * DD + col) =
            pk16(o[nt][2] * inv1, o[nt][3] * inv1);
    }
}

// ---------------- host ---------------------------------------------------------
extern "C" void kernel_launch(void* const* d_in, const int* in_sizes, int n_in,
                              void* d_out, int out_size)
{
    const float* hidden = (const float*)d_in[0];
    const int*   amask  = (const int*)  d_in[1];
    const float* Wq     = (const float*)d_in[2];
    const float* Wk     = (const float*)d_in[3];
    const float* Wv     = (const float*)d_in[4];
    const float* Wo     = (const float*)d_in[5];
    const float* ln1g   = (const float*)d_in[6];
    const float* ln1b   = (const float*)d_in[7];
    const float* W1     = (const float*)d_in[8];
    const float* b1     = (const float*)d_in[9];
    const float* W2     = (const float*)d_in[10];
    const float* b2     = (const float*)d_in[11];
    const float* ln2g   = (const float*)d_in[12];
    const float* ln2b   = (const float*)d_in[13];
    float* out = (float*)d_out;

    __half *x16, *qkv16, *ctx16, *y16, *h16, *w16;
    float* x2;
    cudaGetSymbolAddress((void**)&x16,   g_x16);
    cudaGetSymbolAddress((void**)&qkv16, g_qkv16);
    cudaGetSymbolAddress((void**)&ctx16, g_ctx16);
    cudaGetSymbolAddress((void**)&x2,    g_x2);
    cudaGetSymbolAddress((void**)&y16,   g_y16);
    cudaGetSymbolAddress((void**)&h16,   g_h16);
    cudaGetSymbolAddress((void**)&w16,   g_w16);

    cudaFuncSetAttribute(attn_tc, cudaFuncAttributeMaxDynamicSharedMemorySize,
                         AT_SMEM_BYTES);
    cudaFuncSetAttribute(gemm_f16, cudaFuncAttributeMaxDynamicSharedMemorySize,
                         F16_SMEM);

    const int M = MROWS;

    // all weight transposes in one launch
    trans16all<<<dim3(FF/32, DD/32, 6), 256>>>(Wq, Wk, Wv, Wo, W1, W2, w16);

    // LN1 -> fp16
    ln_f16<<<M, 256>>>(hidden, ln1g, ln1b, x16);
    // fused QKV projection -> fp16 (Q columns pre-scaled by 0.125*log2e)
    gemm_f16<<<dim3(QKVD/128, M/256), 512, F16_SMEM>>>(
        x16, w16, nullptr, nullptr, nullptr, qkv16, M, QKVD, DD, 0, DD);
    // attention -> ctx fp16
    attn_tc<<<dim3(SS/128, BB*HH), 256, AT_SMEM_BYTES>>>(qkv16, amask, ctx16);
    // output projection + residual -> fp32 x2
    gemm_f16<<<dim3(DD/128, M/256), 512, F16_SMEM>>>(
        ctx16, w16 + 3*(size_t)M1, nullptr, hidden, x2, nullptr, M, DD, DD, 0, 0);
    // LN2 -> fp16
    ln_f16<<<M, 256>>>(x2, ln2g, ln2b, y16);
    // FFN1 (bias + SiLU) -> fp16 h
    gemm_f16<<<dim3(FF/128, M/256), 512, F16_SMEM>>>(
        y16, w16 + 4*(size_t)M1, b1, nullptr, nullptr, h16, M, FF, DD, 1, 0);
    // FFN2 (bias + residual x2) -> fp32 out
    gemm_f16<<<dim3(DD/128, M/256), 512, F16_SMEM>>>(
        h16, w16 + 8*(size_t)M1, b2, x2, out, nullptr, M, DD, FF, 0, 0);
}